// round 1
// baseline (speedup 1.0000x reference)
#include <cuda_runtime.h>
#include <cuda_bf16.h>

// Problem shape (fixed for this dataset)
#define BB   8
#define LQ   2048
#define LM   2048
#define DD   1024
#define NEGV (-1000000.0f)

// Scratch (device globals: allocation-free per harness rules)
__device__ float g_q[(size_t)BB * LQ * DD];        // 64 MB: projected query
__device__ float g_logits[(size_t)BB * LQ * LM];   // 128 MB: logits -> softmax weights

// ---------------------------------------------------------------------------
// NT GEMM: C[M,N] = A[M,K] * B[N,K]^T  (+bias[n]) (+mask epilogue)
// A,B row-major with K contiguous. Batched via blockIdx.z.
// Tile 128x128x8, 256 threads, 8x8 per thread.
// ---------------------------------------------------------------------------
template <bool BIAS, bool MASK>
__global__ __launch_bounds__(256)
void gemm_nt_kernel(const float* __restrict__ A, const float* __restrict__ B,
                    float* __restrict__ C, const float* __restrict__ bias,
                    const int* __restrict__ mask, int M, int N, int K)
{
    const int bz = blockIdx.z;
    A += (size_t)bz * M * K;
    B += (size_t)bz * N * K;
    C += (size_t)bz * M * N;
    if (MASK) mask += (size_t)bz * M * N;

    __shared__ float As[8][132];   // padded: conflict-free transposed stores
    __shared__ float Bs[8][132];

    const int tid  = threadIdx.x;
    const int bm   = blockIdx.y * 128;
    const int bn   = blockIdx.x * 128;
    const int lrow = tid >> 1;            // 0..127
    const int lcol = (tid & 1) << 2;      // 0 or 4
    const int tm   = (tid >> 4) << 3;     // 0..120
    const int tn   = (tid & 15) << 3;     // 0..120

    float acc[8][8] = {};
    float fa[8], fb[8];

    for (int k0 = 0; k0 < K; k0 += 8) {
        float4 av = *reinterpret_cast<const float4*>(&A[(size_t)(bm + lrow) * K + k0 + lcol]);
        float4 bv = *reinterpret_cast<const float4*>(&B[(size_t)(bn + lrow) * K + k0 + lcol]);
        As[lcol + 0][lrow] = av.x; As[lcol + 1][lrow] = av.y;
        As[lcol + 2][lrow] = av.z; As[lcol + 3][lrow] = av.w;
        Bs[lcol + 0][lrow] = bv.x; Bs[lcol + 1][lrow] = bv.y;
        Bs[lcol + 2][lrow] = bv.z; Bs[lcol + 3][lrow] = bv.w;
        __syncthreads();
        #pragma unroll
        for (int k = 0; k < 8; k++) {
            #pragma unroll
            for (int i = 0; i < 8; i++) fa[i] = As[k][tm + i];
            #pragma unroll
            for (int j = 0; j < 8; j++) fb[j] = Bs[k][tn + j];
            #pragma unroll
            for (int i = 0; i < 8; i++)
                #pragma unroll
                for (int j = 0; j < 8; j++)
                    acc[i][j] = fmaf(fa[i], fb[j], acc[i][j]);
        }
        __syncthreads();
    }

    #pragma unroll
    for (int i = 0; i < 8; i++) {
        const size_t row = (size_t)(bm + tm + i);
        float out[8];
        #pragma unroll
        for (int j = 0; j < 8; j++) {
            float v = acc[i][j];
            const int col = bn + tn + j;
            if (BIAS) v += bias[col];
            if (MASK) v += mask[row * N + col] ? 0.0f : NEGV;
            out[j] = v;
        }
        float4* cp = reinterpret_cast<float4*>(&C[row * N + bn + tn]);
        cp[0] = make_float4(out[0], out[1], out[2], out[3]);
        cp[1] = make_float4(out[4], out[5], out[6], out[7]);
    }
}

// ---------------------------------------------------------------------------
// NN GEMM: C[M,N] = A[M,K] * B[K,N]   (A: weights, B: memories). Batched via z.
// ---------------------------------------------------------------------------
__global__ __launch_bounds__(256)
void gemm_nn_kernel(const float* __restrict__ A, const float* __restrict__ B,
                    float* __restrict__ C, int M, int N, int K)
{
    const int bz = blockIdx.z;
    A += (size_t)bz * M * K;
    B += (size_t)bz * K * N;
    C += (size_t)bz * M * N;

    __shared__ float As[8][132];
    __shared__ float Bs[8][132];

    const int tid  = threadIdx.x;
    const int bm   = blockIdx.y * 128;
    const int bn   = blockIdx.x * 128;
    const int arow = tid >> 1;
    const int acol = (tid & 1) << 2;
    const int brow = tid >> 5;            // 0..7
    const int bcol = (tid & 31) << 2;     // 0..124
    const int tm   = (tid >> 4) << 3;
    const int tn   = (tid & 15) << 3;

    float acc[8][8] = {};
    float fa[8], fb[8];

    for (int k0 = 0; k0 < K; k0 += 8) {
        float4 av = *reinterpret_cast<const float4*>(&A[(size_t)(bm + arow) * K + k0 + acol]);
        float4 bv = *reinterpret_cast<const float4*>(&B[(size_t)(k0 + brow) * N + bn + bcol]);
        As[acol + 0][arow] = av.x; As[acol + 1][arow] = av.y;
        As[acol + 2][arow] = av.z; As[acol + 3][arow] = av.w;
        *reinterpret_cast<float4*>(&Bs[brow][bcol]) = bv;
        __syncthreads();
        #pragma unroll
        for (int k = 0; k < 8; k++) {
            #pragma unroll
            for (int i = 0; i < 8; i++) fa[i] = As[k][tm + i];
            #pragma unroll
            for (int j = 0; j < 8; j++) fb[j] = Bs[k][tn + j];
            #pragma unroll
            for (int i = 0; i < 8; i++)
                #pragma unroll
                for (int j = 0; j < 8; j++)
                    acc[i][j] = fmaf(fa[i], fb[j], acc[i][j]);
        }
        __syncthreads();
    }

    #pragma unroll
    for (int i = 0; i < 8; i++) {
        const size_t row = (size_t)(bm + tm + i);
        float4* cp = reinterpret_cast<float4*>(&C[row * N + bn + tn]);
        cp[0] = make_float4(acc[i][0], acc[i][1], acc[i][2], acc[i][3]);
        cp[1] = make_float4(acc[i][4], acc[i][5], acc[i][6], acc[i][7]);
    }
}

// ---------------------------------------------------------------------------
// Row softmax over LM=2048, in place. One block (256 threads) per row.
// ---------------------------------------------------------------------------
__global__ __launch_bounds__(256)
void softmax_kernel(float* __restrict__ x)
{
    float* row = x + (size_t)blockIdx.x * LM;
    const int t = threadIdx.x;
    __shared__ float smax[8];
    __shared__ float ssum[8];

    float v[8];
    float m = -3.0e38f;
    #pragma unroll
    for (int i = 0; i < 8; i++) {
        v[i] = row[t + i * 256];
        m = fmaxf(m, v[i]);
    }
    #pragma unroll
    for (int o = 16; o > 0; o >>= 1) m = fmaxf(m, __shfl_xor_sync(0xFFFFFFFFu, m, o));
    if ((t & 31) == 0) smax[t >> 5] = m;
    __syncthreads();
    m = smax[0];
    #pragma unroll
    for (int i = 1; i < 8; i++) m = fmaxf(m, smax[i]);

    float s = 0.0f;
    #pragma unroll
    for (int i = 0; i < 8; i++) {
        v[i] = expf(v[i] - m);
        s += v[i];
    }
    #pragma unroll
    for (int o = 16; o > 0; o >>= 1) s += __shfl_xor_sync(0xFFFFFFFFu, s, o);
    if ((t & 31) == 0) ssum[t >> 5] = s;
    __syncthreads();
    s = 0.0f;
    #pragma unroll
    for (int i = 0; i < 8; i++) s += ssum[i];
    const float inv = 1.0f / s;

    #pragma unroll
    for (int i = 0; i < 8; i++) row[t + i * 256] = v[i] * inv;
}

// ---------------------------------------------------------------------------
extern "C" void kernel_launch(void* const* d_in, const int* in_sizes, int n_in,
                              void* d_out, int out_size)
{
    (void)in_sizes; (void)n_in; (void)out_size;
    const float* query    = (const float*)d_in[0];  // [8,2048,1024]
    const float* memories = (const float*)d_in[1];  // [8,2048,1024]
    const int*   mask     = (const int*)d_in[2];    // [8,2048,2048]
    const float* W        = (const float*)d_in[3];  // [1024,1024]
    const float* bvec     = (const float*)d_in[4];  // [1024]
    float*       out      = (float*)d_out;          // [8,2048,1024]

    float* q      = nullptr;
    float* logits = nullptr;
    cudaGetSymbolAddress((void**)&q,      g_q);
    cudaGetSymbolAddress((void**)&logits, g_logits);

    // 1) q = query @ W^T + b   (M=16384, N=1024, K=1024; single "batch")
    gemm_nt_kernel<true, false><<<dim3(DD / 128, (BB * LQ) / 128, 1), 256>>>(
        query, W, q, bvec, nullptr, BB * LQ, DD, DD);

    // 2) logits = q @ mem^T + (1-mask)*NEG   (per batch: 2048x2048x1024)
    gemm_nt_kernel<false, true><<<dim3(LM / 128, LQ / 128, BB), 256>>>(
        q, memories, logits, nullptr, mask, LQ, LM, DD);

    // 3) softmax rows (in place)
    softmax_kernel<<<BB * LQ, 256>>>(logits);

    // 4) out = weights @ mem   (per batch: 2048x1024x2048)
    gemm_nn_kernel<<<dim3(DD / 128, LQ / 128, BB), 256>>>(
        logits, memories, out, LQ, DD, LM);
}

// round 4
// speedup vs baseline: 1.8057x; 1.8057x over previous
#include <cuda_runtime.h>
#include <cuda_bf16.h>
#include <cstdint>

#define BB 8
#define LQ 2048
#define LM 2048
#define DD 1024
#define NEGV (-1000000.0f)

// ------------------------- scratch (device globals) -------------------------
__device__ __nv_bfloat16 g_qryhi[(size_t)BB*LQ*DD], g_qrylo[(size_t)BB*LQ*DD];
__device__ __nv_bfloat16 g_Whi[(size_t)DD*DD],      g_Wlo[(size_t)DD*DD];
__device__ __nv_bfloat16 g_qhi[(size_t)BB*LQ*DD],   g_qlo[(size_t)BB*LQ*DD];
__device__ __nv_bfloat16 g_mhi[(size_t)BB*LM*DD],   g_mlo[(size_t)BB*LM*DD];
__device__ __nv_bfloat16 g_mThi[(size_t)BB*DD*LM],  g_mTlo[(size_t)BB*DD*LM];
__device__ float         g_logits[(size_t)BB*LQ*LM];
__device__ __nv_bfloat16 g_whi[(size_t)BB*LQ*LM],   g_wlo[(size_t)BB*LQ*LM];

// ------------------------- helpers -------------------------
__device__ __forceinline__ uint32_t smem_u32(const void* p) {
    uint32_t a;
    asm("{ .reg .u64 t; cvta.to.shared.u64 t, %1; cvt.u32.u64 %0, t; }" : "=r"(a) : "l"(p));
    return a;
}
__device__ __forceinline__ void cp16(uint32_t s, const void* g) {
    asm volatile("cp.async.cg.shared.global [%0], [%1], 16;" :: "r"(s), "l"(g));
}
__device__ __forceinline__ void ldmx4(uint32_t* r, uint32_t a) {
    asm volatile("ldmatrix.sync.aligned.m8n8.x4.shared.b16 {%0,%1,%2,%3}, [%4];"
                 : "=r"(r[0]), "=r"(r[1]), "=r"(r[2]), "=r"(r[3]) : "r"(a));
}
__device__ __forceinline__ void mma16816(float* c, const uint32_t* a, uint32_t b0, uint32_t b1) {
    asm volatile(
        "mma.sync.aligned.m16n8k16.row.col.f32.bf16.bf16.f32 "
        "{%0,%1,%2,%3}, {%4,%5,%6,%7}, {%8,%9}, {%0,%1,%2,%3};"
        : "+f"(c[0]), "+f"(c[1]), "+f"(c[2]), "+f"(c[3])
        : "r"(a[0]), "r"(a[1]), "r"(a[2]), "r"(a[3]), "r"(b0), "r"(b1));
}

// ------------------------- split-bf16 mma.sync GEMM (NT, K-major) -------------------------
// C[M,N] = (Ahi+Alo)[M,K] * (Bhi+Blo)[N,K]^T, 3 MMA terms, fp32 accum.
// EPI: 1 = +bias -> split bf16 Chi/Clo ; 2 = +mask NEG -> fp32 Cf ; 3 = plain -> fp32 Cf

// SMEM tile: 128 rows x 32 bf16, row stride 80 bytes (64B data + 16B pad).
#define ROWB 80
#define TILEB (128 * ROWB)          // 10240 B
#define STAGEB (4 * TILEB)          // Ah, Al, Bh, Bl = 40960 B
#define NSTAGE 2

__device__ __forceinline__ void load_tile32(uint32_t stile, const __nv_bfloat16* g,
                                            int K, int k0, int tid) {
    #pragma unroll
    for (int p = 0; p < 2; p++) {
        int idx = p * 256 + tid;          // 0..511
        int row = idx & 127;
        int c   = idx >> 7;               // 0..3 (16B chunk within 64B row)
        cp16(stile + (uint32_t)row * ROWB + (uint32_t)c * 16,
             g + (size_t)row * K + k0 + c * 8);
    }
}

template<int EPI>
__global__ __launch_bounds__(256)
void gemm_mma(const __nv_bfloat16* __restrict__ Ahi, const __nv_bfloat16* __restrict__ Alo,
              const __nv_bfloat16* __restrict__ Bhi, const __nv_bfloat16* __restrict__ Blo,
              const float* __restrict__ bias, const int* __restrict__ mask,
              float* __restrict__ Cf,
              __nv_bfloat16* __restrict__ Chi, __nv_bfloat16* __restrict__ Clo,
              int M, int N, int K, size_t sA, size_t sB, size_t sC)
{
    extern __shared__ char dynsmem[];
    const int tid  = threadIdx.x;
    const int bz   = blockIdx.z;
    const int bm   = blockIdx.y * 128;
    const int bn   = blockIdx.x * 128;
    const int wid  = tid >> 5;
    const int lane = tid & 31;
    const int wm   = (wid >> 2) * 64;     // 0, 64
    const int wn   = (wid & 3) * 32;      // 0, 32, 64, 96

    const uint32_t sb = smem_u32(dynsmem);

    const __nv_bfloat16* pAh = Ahi + (size_t)bz * sA + (size_t)bm * K;
    const __nv_bfloat16* pAl = Alo + (size_t)bz * sA + (size_t)bm * K;
    const __nv_bfloat16* pBh = Bhi + (size_t)bz * sB + (size_t)bn * K;
    const __nv_bfloat16* pBl = Blo + (size_t)bz * sB + (size_t)bn * K;

    float acc[4][4][4];
    #pragma unroll
    for (int i = 0; i < 4; i++)
        #pragma unroll
        for (int j = 0; j < 4; j++)
            #pragma unroll
            for (int r = 0; r < 4; r++) acc[i][j][r] = 0.0f;

    const int nk = K >> 5;   // 32-wide k-chunks

    // prologue: stage 0
    {
        uint32_t st = sb;
        load_tile32(st + 0*TILEB, pAh, K, 0, tid);
        load_tile32(st + 1*TILEB, pAl, K, 0, tid);
        load_tile32(st + 2*TILEB, pBh, K, 0, tid);
        load_tile32(st + 3*TILEB, pBl, K, 0, tid);
        asm volatile("cp.async.commit_group;" ::: "memory");
    }

    // ldmatrix base addresses (per-thread row within tiles)
    const uint32_t lrow  = (uint32_t)(lane & 15) * ROWB + (uint32_t)(lane >> 4) * 16;

    for (int c = 0; c < nk; ++c) {
        if (c + 1 < nk) {
            uint32_t st = sb + ((c + 1) & 1) * STAGEB;
            int k0 = (c + 1) << 5;
            load_tile32(st + 0*TILEB, pAh, K, k0, tid);
            load_tile32(st + 1*TILEB, pAl, K, k0, tid);
            load_tile32(st + 2*TILEB, pBh, K, k0, tid);
            load_tile32(st + 3*TILEB, pBl, K, k0, tid);
            asm volatile("cp.async.commit_group;" ::: "memory");
            asm volatile("cp.async.wait_group 1;" ::: "memory");
        } else {
            asm volatile("cp.async.wait_group 0;" ::: "memory");
        }
        __syncthreads();

        const uint32_t st = sb + (c & 1) * STAGEB;
        const uint32_t aH = st + 0*TILEB + (uint32_t)wm * ROWB + lrow;
        const uint32_t aL = st + 1*TILEB + (uint32_t)wm * ROWB + lrow;
        const uint32_t bH = st + 2*TILEB + (uint32_t)wn * ROWB + lrow;
        const uint32_t bL = st + 3*TILEB + (uint32_t)wn * ROWB + lrow;

        #pragma unroll
        for (int k16 = 0; k16 < 2; k16++) {
            const uint32_t ko = (uint32_t)k16 * 32;
            uint32_t ah[4][4], al[4][4], bh[2][4], bl[2][4];
            #pragma unroll
            for (int mt = 0; mt < 4; mt++) {
                ldmx4(ah[mt], aH + (uint32_t)mt * (16 * ROWB) + ko);
                ldmx4(al[mt], aL + (uint32_t)mt * (16 * ROWB) + ko);
            }
            #pragma unroll
            for (int h = 0; h < 2; h++) {
                ldmx4(bh[h], bH + (uint32_t)h * (16 * ROWB) + ko);
                ldmx4(bl[h], bL + (uint32_t)h * (16 * ROWB) + ko);
            }
            #pragma unroll
            for (int mt = 0; mt < 4; mt++) {
                #pragma unroll
                for (int nt = 0; nt < 4; nt++) {
                    const int g = nt >> 1, s = nt & 1;
                    const uint32_t b0h = bh[g][s], b1h = bh[g][s + 2];
                    const uint32_t b0l = bl[g][s], b1l = bl[g][s + 2];
                    mma16816(acc[mt][nt], ah[mt], b0h, b1h);
                    mma16816(acc[mt][nt], ah[mt], b0l, b1l);
                    mma16816(acc[mt][nt], al[mt], b0h, b1h);
                }
            }
        }
        __syncthreads();
    }

    // ---------------- epilogue ----------------
    const int r0 = lane >> 2;            // 0..7
    const int c0 = (lane & 3) * 2;       // 0,2,4,6

    #pragma unroll
    for (int mt = 0; mt < 4; mt++) {
        #pragma unroll
        for (int half = 0; half < 2; half++) {
            const size_t grow = (size_t)(bm + wm + mt * 16 + r0 + half * 8);
            #pragma unroll
            for (int nt = 0; nt < 4; nt++) {
                const int gcol = bn + wn + nt * 8 + c0;
                float v0 = acc[mt][nt][half * 2 + 0];
                float v1 = acc[mt][nt][half * 2 + 1];

                if (EPI == 1) {
                    v0 += bias[gcol];
                    v1 += bias[gcol + 1];
                    __nv_bfloat16 h0 = __float2bfloat16(v0);
                    __nv_bfloat16 h1 = __float2bfloat16(v1);
                    __nv_bfloat16 l0 = __float2bfloat16(v0 - __bfloat162float(h0));
                    __nv_bfloat16 l1 = __float2bfloat16(v1 - __bfloat162float(h1));
                    uint32_t ph = ((uint32_t)__bfloat16_as_ushort(h1) << 16) | __bfloat16_as_ushort(h0);
                    uint32_t pl = ((uint32_t)__bfloat16_as_ushort(l1) << 16) | __bfloat16_as_ushort(l0);
                    *(uint32_t*)(Chi + (size_t)bz * sC + grow * N + gcol) = ph;
                    *(uint32_t*)(Clo + (size_t)bz * sC + grow * N + gcol) = pl;
                } else if (EPI == 2) {
                    int2 mm = *(const int2*)(mask + (size_t)bz * sC + grow * N + gcol);
                    float2 vv;
                    vv.x = v0 + (mm.x ? 0.0f : NEGV);
                    vv.y = v1 + (mm.y ? 0.0f : NEGV);
                    *(float2*)(Cf + (size_t)bz * sC + grow * N + gcol) = vv;
                } else {
                    *(float2*)(Cf + (size_t)bz * sC + grow * N + gcol) = make_float2(v0, v1);
                }
            }
        }
    }
}

// ------------------------- elementwise split fp32 -> (hi,lo) bf16 -------------------------
__global__ __launch_bounds__(256)
void split_kernel(const float* __restrict__ x, __nv_bfloat16* __restrict__ hi,
                  __nv_bfloat16* __restrict__ lo, size_t n)
{
    size_t i = ((size_t)blockIdx.x * 256 + threadIdx.x) * 4;
    if (i >= n) return;
    float4 v = *(const float4*)(x + i);
    float f[4] = {v.x, v.y, v.z, v.w};
    uint32_t ph[2], pl[2];
    #pragma unroll
    for (int j = 0; j < 2; j++) {
        __nv_bfloat16 h0 = __float2bfloat16(f[2*j]);
        __nv_bfloat16 h1 = __float2bfloat16(f[2*j+1]);
        __nv_bfloat16 l0 = __float2bfloat16(f[2*j]   - __bfloat162float(h0));
        __nv_bfloat16 l1 = __float2bfloat16(f[2*j+1] - __bfloat162float(h1));
        ph[j] = ((uint32_t)__bfloat16_as_ushort(h1) << 16) | __bfloat16_as_ushort(h0);
        pl[j] = ((uint32_t)__bfloat16_as_ushort(l1) << 16) | __bfloat16_as_ushort(l0);
    }
    *(uint2*)(hi + i) = make_uint2(ph[0], ph[1]);
    *(uint2*)(lo + i) = make_uint2(pl[0], pl[1]);
}

// ------------------------- bf16 transpose: [R,C] -> [C,R] per batch -------------------------
__global__ __launch_bounds__(256)
void transpose_kernel(const __nv_bfloat16* __restrict__ src, __nv_bfloat16* __restrict__ dst,
                      int R, int C)
{
    __shared__ __nv_bfloat16 t[32][33];
    const int z = blockIdx.z;
    src += (size_t)z * R * C;
    dst += (size_t)z * R * C;
    const int c0 = blockIdx.x * 32, r0 = blockIdx.y * 32;
    #pragma unroll
    for (int i = 0; i < 4; i++)
        t[threadIdx.y + 8*i][threadIdx.x] =
            src[(size_t)(r0 + threadIdx.y + 8*i) * C + c0 + threadIdx.x];
    __syncthreads();
    #pragma unroll
    for (int i = 0; i < 4; i++)
        dst[(size_t)(c0 + threadIdx.y + 8*i) * R + r0 + threadIdx.x] =
            t[threadIdx.x][threadIdx.y + 8*i];
}

// ------------------------- row softmax over LM, writes split-bf16 weights -------------------------
__global__ __launch_bounds__(256)
void softmax_split(const float* __restrict__ x, __nv_bfloat16* __restrict__ whi,
                   __nv_bfloat16* __restrict__ wlo)
{
    const float* row = x + (size_t)blockIdx.x * LM;
    __nv_bfloat16* rh = whi + (size_t)blockIdx.x * LM;
    __nv_bfloat16* rl = wlo + (size_t)blockIdx.x * LM;
    const int t = threadIdx.x;
    __shared__ float smax[8], ssum[8];

    float v[8];
    float m = -3.0e38f;
    #pragma unroll
    for (int i = 0; i < 8; i++) { v[i] = row[t + i*256]; m = fmaxf(m, v[i]); }
    #pragma unroll
    for (int o = 16; o > 0; o >>= 1) m = fmaxf(m, __shfl_xor_sync(0xFFFFFFFFu, m, o));
    if ((t & 31) == 0) smax[t >> 5] = m;
    __syncthreads();
    m = smax[0];
    #pragma unroll
    for (int i = 1; i < 8; i++) m = fmaxf(m, smax[i]);

    float s = 0.0f;
    #pragma unroll
    for (int i = 0; i < 8; i++) { v[i] = expf(v[i] - m); s += v[i]; }
    #pragma unroll
    for (int o = 16; o > 0; o >>= 1) s += __shfl_xor_sync(0xFFFFFFFFu, s, o);
    if ((t & 31) == 0) ssum[t >> 5] = s;
    __syncthreads();
    s = 0.0f;
    #pragma unroll
    for (int i = 0; i < 8; i++) s += ssum[i];
    const float inv = 1.0f / s;

    #pragma unroll
    for (int i = 0; i < 8; i++) {
        float w = v[i] * inv;
        __nv_bfloat16 h = __float2bfloat16(w);
        __nv_bfloat16 l = __float2bfloat16(w - __bfloat162float(h));
        rh[t + i*256] = h;
        rl[t + i*256] = l;
    }
}

// ------------------------- launch -------------------------
extern "C" void kernel_launch(void* const* d_in, const int* in_sizes, int n_in,
                              void* d_out, int out_size)
{
    (void)in_sizes; (void)n_in; (void)out_size;
    const float* query    = (const float*)d_in[0];
    const float* memories = (const float*)d_in[1];
    const int*   mask     = (const int*)d_in[2];
    const float* W        = (const float*)d_in[3];
    const float* bvec     = (const float*)d_in[4];
    float*       out      = (float*)d_out;

    __nv_bfloat16 *qryhi, *qrylo, *Whi, *Wlo, *qhi, *qlo, *mhi, *mlo, *mThi, *mTlo, *whi, *wlo;
    float *logits;
    cudaGetSymbolAddress((void**)&qryhi, g_qryhi);  cudaGetSymbolAddress((void**)&qrylo, g_qrylo);
    cudaGetSymbolAddress((void**)&Whi,   g_Whi);    cudaGetSymbolAddress((void**)&Wlo,   g_Wlo);
    cudaGetSymbolAddress((void**)&qhi,   g_qhi);    cudaGetSymbolAddress((void**)&qlo,   g_qlo);
    cudaGetSymbolAddress((void**)&mhi,   g_mhi);    cudaGetSymbolAddress((void**)&mlo,   g_mlo);
    cudaGetSymbolAddress((void**)&mThi,  g_mThi);   cudaGetSymbolAddress((void**)&mTlo,  g_mTlo);
    cudaGetSymbolAddress((void**)&whi,   g_whi);    cudaGetSymbolAddress((void**)&wlo,   g_wlo);
    cudaGetSymbolAddress((void**)&logits, g_logits);

    const int SMEM = NSTAGE * STAGEB;   // 81920 B
    cudaFuncSetAttribute(gemm_mma<1>, cudaFuncAttributeMaxDynamicSharedMemorySize, SMEM);
    cudaFuncSetAttribute(gemm_mma<2>, cudaFuncAttributeMaxDynamicSharedMemorySize, SMEM);
    cudaFuncSetAttribute(gemm_mma<3>, cudaFuncAttributeMaxDynamicSharedMemorySize, SMEM);

    const size_t nQ = (size_t)BB * LQ * DD;
    const size_t nW = (size_t)DD * DD;

    // 0) split inputs to (hi, lo) bf16
    split_kernel<<<(unsigned)(nQ / 1024), 256>>>(query,    qryhi, qrylo, nQ);
    split_kernel<<<(unsigned)(nQ / 1024), 256>>>(memories, mhi,   mlo,   nQ);
    split_kernel<<<(unsigned)(nW / 1024), 256>>>(W,        Whi,   Wlo,   nW);

    // 0b) transpose memories (per batch [Lm,D] -> [D,Lm]) for the AV GEMM
    transpose_kernel<<<dim3(DD/32, LM/32, BB), dim3(32, 8)>>>(mhi, mThi, LM, DD);
    transpose_kernel<<<dim3(DD/32, LM/32, BB), dim3(32, 8)>>>(mlo, mTlo, LM, DD);

    // 1) q = query @ W^T + b -> split bf16   (M=16384, N=1024, K=1024)
    gemm_mma<1><<<dim3(DD/128, (BB*LQ)/128, 1), 256, SMEM>>>(
        qryhi, qrylo, Whi, Wlo, bvec, nullptr, nullptr, qhi, qlo,
        BB*LQ, DD, DD, (size_t)0, (size_t)0, (size_t)0);

    // 2) logits = q @ mem^T + mask  (per batch 2048x2048x1024) -> fp32
    gemm_mma<2><<<dim3(LM/128, LQ/128, BB), 256, SMEM>>>(
        qhi, qlo, mhi, mlo, nullptr, mask, logits, nullptr, nullptr,
        LQ, LM, DD, (size_t)LQ*DD, (size_t)LM*DD, (size_t)LQ*LM);

    // 3) softmax -> split bf16 weights
    softmax_split<<<BB*LQ, 256>>>(logits, whi, wlo);

    // 4) out = weights @ memT^T   (per batch 2048x1024x2048) -> fp32
    gemm_mma<3><<<dim3(DD/128, LQ/128, BB), 256, SMEM>>>(
        whi, wlo, mThi, mTlo, nullptr, nullptr, out, nullptr, nullptr,
        LQ, DD, LM, (size_t)LQ*LM, (size_t)DD*LM, (size_t)LQ*DD);
}